// round 12
// baseline (speedup 1.0000x reference)
#include <cuda_runtime.h>

// ============================================================================
// RNN_41936060678228: autoregressive LSTM wavefunction
// B=2048, L=512, F=64, K=2. Output = float32 amp only.
//
// Round-9: 2-way k-split warp pairs. 128 CTAs x 256 threads (8 warps =
// 2/SMSP for latency hiding). Pair (w, w+4) owns 4 samples; role 0 computes
// k in [0,32), role 1 k in [32,64) -> per-warp weight traffic halved (L1
// stays ~256KB/step/SM) while FMA floor stays 2048 cyc/SMSP/step.
// Partials exchanged via SMEM (f32x2 adds) with pairwise named barriers.
// h stored duplicated {h,h} so fma.rn.f32x2 multiplier loads are direct
// ulonglong2 LDS (no pack MOVs). Gates split per role (2 samples each).
// ============================================================================

typedef unsigned long long ULL;

__device__ __align__(16) float g_Whp[64 * 256];
__device__ __align__(16) float g_u[2 * 256];
__device__ __align__(16) float g_wd[64];
__device__ float g_bd[1];

__device__ __forceinline__ ULL fma2(ULL a, ULL b, ULL c) {
    ULL d;
    asm("fma.rn.f32x2 %0, %1, %2, %3;" : "=l"(d) : "l"(a), "l"(b), "l"(c));
    return d;
}
__device__ __forceinline__ ULL add2(ULL a, ULL b) {
    ULL d;
    asm("add.rn.f32x2 %0, %1, %2;" : "=l"(d) : "l"(a), "l"(b));
    return d;
}
__device__ __forceinline__ void upk2(float& lo, float& hi, ULL p) {
    asm("mov.b64 {%0, %1}, %2;" : "=f"(lo), "=f"(hi) : "l"(p));
}
__device__ __forceinline__ float tanhap(float x) {
    float t;
    asm("tanh.approx.f32 %0, %1;" : "=f"(t) : "f"(x));
    return t;
}
__device__ __forceinline__ float sigt(float x) {
    return fmaf(tanhap(0.5f * x), 0.5f, 0.5f);
}
__device__ __forceinline__ float softplusf(float x) {
    float ax = fabsf(x);
    return fmaxf(x, 0.0f) + __logf(1.0f + __expf(-ax));
}

// ---------------------------------------------------------------------------
// Prep: gate-interleave Wh columns: pj = 4*n + gate (i,f,g,o), j = gate*64+n.
// ---------------------------------------------------------------------------
__global__ void prep_kernel(const float* __restrict__ W0, const float* __restrict__ b0,
                            const float* __restrict__ Wi, const float* __restrict__ Wh,
                            const float* __restrict__ bh, const float* __restrict__ Wa,
                            const float* __restrict__ ba) {
    int idx = blockIdx.x * blockDim.x + threadIdx.x;
    if (idx < 16384) {
        int k = idx >> 8, pj = idx & 255;
        int n = pj >> 2, gate = pj & 3;
        g_Whp[k * 256 + pj] = Wh[k * 256 + gate * 64 + n];
    } else if (idx < 16896) {
        int t = idx - 16384;
        int tok = t >> 8, pj = t & 255;
        int n = pj >> 2, gate = pj & 3;
        int j = gate * 64 + n;
        float acc = bh[j];
        for (int f = 0; f < 64; f++)
            acc += (W0[tok * 64 + f] + b0[f]) * Wi[f * 256 + j];
        g_u[tok * 256 + pj] = acc;
    } else if (idx < 16960) {
        int n = idx - 16896;
        g_wd[n] = Wa[n * 2 + 1] - Wa[n * 2 + 0];
    } else if (idx == 16960) {
        g_bd[0] = ba[1] - ba[0];
    }
}

// ---------------------------------------------------------------------------
__global__ __launch_bounds__(256) void lstm_kernel(const int* __restrict__ s,
                                                   float* __restrict__ out,
                                                   int B, int L) {
    __shared__ float sU[512];
    __shared__ float sWd[64];
    __shared__ __align__(16) float sH[16 * 128];     // {h,h} dup, 8KB
    __shared__ ULL sX[4][2][8][32];                  // exchange, 16KB

    int tid = threadIdx.x;
    for (int i = tid; i < 512; i += 256) sU[i] = g_u[i];
    if (tid < 64) sWd[tid] = g_wd[tid];
    for (int i = tid; i < 2048; i += 256) sH[i] = 0.0f;
    __syncthreads();

    const float bd = g_bd[0];
    int lane = tid & 31, warp = tid >> 5;
    int pair = warp & 3, role = warp >> 2;
    int base = blockIdx.x * 16 + pair * 4;
    int barid = pair + 1;

    const int i0 = lane, i1 = lane + 32;
    const float wdl = sWd[lane], wdh = sWd[lane + 32];
    const ulonglong2* __restrict__ Wq = (const ulonglong2*)g_Whp; // row k: +k*64

    float* hd0 = sH + (pair * 4 + 0) * 128;
    float* hd1 = hd0 + 128;
    float* hd2 = hd0 + 256;
    float* hd3 = hd0 + 384;

    float c0 = 0.f, c1 = 0.f, c2 = 0.f, c3 = 0.f;   // owned 2 samples x 2 cells
    float ampa = 0.f, ampb = 0.f;
    int tok0 = 0, tok1 = 0, tok2 = 0, tok3 = 0;     // used by role 0 only

    long long gi0 = min(base + 0, B - 1), gi1 = min(base + 1, B - 1);
    long long gi2 = min(base + 2, B - 1), gi3 = min(base + 3, B - 1);
    const int* sr0 = s + gi0 * L;
    const int* sr1 = s + gi1 * L;
    const int* sr2 = s + gi2 * L;
    const int* sr3 = s + gi3 * L;

    const int krow = role * 32;

    for (int t = 0; t < L; t++) {
        int sp0 = 0, sp1 = 0, sp2 = 0, sp3 = 0;
        if (role == 0) {
            sp0 = __ldg(sr0 + t); sp1 = __ldg(sr1 + t);
            sp2 = __ldg(sr2 + t); sp3 = __ldg(sr3 + t);
        } else {
            sp2 = __ldg(sr2 + t); sp3 = __ldg(sr3 + t);
        }

        // accumulators: a<sample><0..3>; role 0 seeds with u[tok], role 1 zero
        ULL a00, a01, a02, a03, a10, a11, a12, a13;
        ULL a20, a21, a22, a23, a30, a31, a32, a33;
        if (role == 0) {
            const ulonglong2* uq0 = (const ulonglong2*)(sU + (tok0 << 8));
            const ulonglong2* uq1 = (const ulonglong2*)(sU + (tok1 << 8));
            const ulonglong2* uq2 = (const ulonglong2*)(sU + (tok2 << 8));
            const ulonglong2* uq3 = (const ulonglong2*)(sU + (tok3 << 8));
            ulonglong2 u0l = uq0[i0], u0h = uq0[i1];
            ulonglong2 u1l = uq1[i0], u1h = uq1[i1];
            ulonglong2 u2l = uq2[i0], u2h = uq2[i1];
            ulonglong2 u3l = uq3[i0], u3h = uq3[i1];
            a00 = u0l.x; a01 = u0l.y; a02 = u0h.x; a03 = u0h.y;
            a10 = u1l.x; a11 = u1l.y; a12 = u1h.x; a13 = u1h.y;
            a20 = u2l.x; a21 = u2l.y; a22 = u2h.x; a23 = u2h.y;
            a30 = u3l.x; a31 = u3l.y; a32 = u3h.x; a33 = u3h.y;
        } else {
            a00 = a01 = a02 = a03 = a10 = a11 = a12 = a13 = 0ULL;
            a20 = a21 = a22 = a23 = a30 = a31 = a32 = a33 = 0ULL;
        }

        // ---- k-loop over this role's 32 rows ----
#pragma unroll 4
        for (int kb = 0; kb < 32; kb += 4) {
            int k = krow + kb;
            ulonglong2 wl0 = __ldg(Wq + (k + 0) * 64 + i0);
            ulonglong2 wh0 = __ldg(Wq + (k + 0) * 64 + i1);
            ulonglong2 wl1 = __ldg(Wq + (k + 1) * 64 + i0);
            ulonglong2 wh1 = __ldg(Wq + (k + 1) * 64 + i1);
            ulonglong2 wl2 = __ldg(Wq + (k + 2) * 64 + i0);
            ulonglong2 wh2 = __ldg(Wq + (k + 2) * 64 + i1);
            ulonglong2 wl3 = __ldg(Wq + (k + 3) * 64 + i0);
            ulonglong2 wh3 = __ldg(Wq + (k + 3) * 64 + i1);

            // duplicated h: .x = {h[k],h[k]}, .y = {h[k+1],h[k+1]}
            ulonglong2 H0a = *(const ulonglong2*)(hd0 + k * 2);
            ulonglong2 H0b = *(const ulonglong2*)(hd0 + k * 2 + 4);
            ulonglong2 H1a = *(const ulonglong2*)(hd1 + k * 2);
            ulonglong2 H1b = *(const ulonglong2*)(hd1 + k * 2 + 4);
            ulonglong2 H2a = *(const ulonglong2*)(hd2 + k * 2);
            ulonglong2 H2b = *(const ulonglong2*)(hd2 + k * 2 + 4);
            ulonglong2 H3a = *(const ulonglong2*)(hd3 + k * 2);
            ulonglong2 H3b = *(const ulonglong2*)(hd3 + k * 2 + 4);

#define STEP_K(WL, WH, M0, M1, M2, M3)                                        \
            a00 = fma2(M0, WL.x, a00); a01 = fma2(M0, WL.y, a01);             \
            a02 = fma2(M0, WH.x, a02); a03 = fma2(M0, WH.y, a03);             \
            a10 = fma2(M1, WL.x, a10); a11 = fma2(M1, WL.y, a11);             \
            a12 = fma2(M1, WH.x, a12); a13 = fma2(M1, WH.y, a13);             \
            a20 = fma2(M2, WL.x, a20); a21 = fma2(M2, WL.y, a21);             \
            a22 = fma2(M2, WH.x, a22); a23 = fma2(M2, WH.y, a23);             \
            a30 = fma2(M3, WL.x, a30); a31 = fma2(M3, WL.y, a31);             \
            a32 = fma2(M3, WH.x, a32); a33 = fma2(M3, WH.y, a33);

            STEP_K(wl0, wh0, H0a.x, H1a.x, H2a.x, H3a.x)
            STEP_K(wl1, wh1, H0a.y, H1a.y, H2a.y, H3a.y)
            STEP_K(wl2, wh2, H0b.x, H1b.x, H2b.x, H3b.x)
            STEP_K(wl3, wh3, H0b.y, H1b.y, H2b.y, H3b.y)
#undef STEP_K
        }

        // ---- exchange partials: store NOT-owned samples, add owned ----
        if (role == 0) {
            sX[pair][0][0][lane] = a20; sX[pair][0][1][lane] = a21;
            sX[pair][0][2][lane] = a22; sX[pair][0][3][lane] = a23;
            sX[pair][0][4][lane] = a30; sX[pair][0][5][lane] = a31;
            sX[pair][0][6][lane] = a32; sX[pair][0][7][lane] = a33;
        } else {
            sX[pair][1][0][lane] = a00; sX[pair][1][1][lane] = a01;
            sX[pair][1][2][lane] = a02; sX[pair][1][3][lane] = a03;
            sX[pair][1][4][lane] = a10; sX[pair][1][5][lane] = a11;
            sX[pair][1][6][lane] = a12; sX[pair][1][7][lane] = a13;
        }
        asm volatile("bar.sync %0, 64;" :: "r"(barid));
        float hv0, hv1, hv2, hv3;
        if (role == 0) {
            a00 = add2(a00, sX[pair][1][0][lane]); a01 = add2(a01, sX[pair][1][1][lane]);
            a02 = add2(a02, sX[pair][1][2][lane]); a03 = add2(a03, sX[pair][1][3][lane]);
            a10 = add2(a10, sX[pair][1][4][lane]); a11 = add2(a11, sX[pair][1][5][lane]);
            a12 = add2(a12, sX[pair][1][6][lane]); a13 = add2(a13, sX[pair][1][7][lane]);
#define GATES(A0, A1, CREG, HOUT)                                             \
            {                                                                 \
                float gi, gf, gg, go;                                         \
                upk2(gi, gf, A0); upk2(gg, go, A1);                           \
                float cn = fmaf(sigt(gf), CREG, sigt(gi) * tanhap(gg));       \
                CREG = cn; HOUT = sigt(go) * tanhap(cn);                      \
            }
            GATES(a00, a01, c0, hv0) GATES(a02, a03, c1, hv1)
            GATES(a10, a11, c2, hv2) GATES(a12, a13, c3, hv3)
        } else {
            a20 = add2(a20, sX[pair][0][0][lane]); a21 = add2(a21, sX[pair][0][1][lane]);
            a22 = add2(a22, sX[pair][0][2][lane]); a23 = add2(a23, sX[pair][0][3][lane]);
            a30 = add2(a30, sX[pair][0][4][lane]); a31 = add2(a31, sX[pair][0][5][lane]);
            a32 = add2(a32, sX[pair][0][6][lane]); a33 = add2(a33, sX[pair][0][7][lane]);
            GATES(a20, a21, c0, hv0) GATES(a22, a23, c1, hv1)
            GATES(a30, a31, c2, hv2) GATES(a32, a33, c3, hv3)
#undef GATES
        }

        // ---- store duplicated h for owned samples ----
        float* ho0 = role ? hd2 : hd0;
        float* ho1 = role ? hd3 : hd1;
        *(float2*)(ho0 + lane * 2)        = make_float2(hv0, hv0);
        *(float2*)(ho0 + (lane + 32) * 2) = make_float2(hv1, hv1);
        *(float2*)(ho1 + lane * 2)        = make_float2(hv2, hv2);
        *(float2*)(ho1 + (lane + 32) * 2) = make_float2(hv3, hv3);
        asm volatile("bar.sync %0, 64;" :: "r"(barid));

        // ---- logp for owned 2 samples ----
        float pa = fmaf(hv0, wdl, hv1 * wdh);
        float pb = fmaf(hv2, wdl, hv3 * wdh);
#pragma unroll
        for (int m = 16; m; m >>= 1) {
            pa += __shfl_xor_sync(0xffffffffu, pa, m);
            pb += __shfl_xor_sync(0xffffffffu, pb, m);
        }
        int spa = role ? sp2 : sp0;
        int spb = role ? sp3 : sp1;
        float da = pa + bd, db = pb + bd;
        ampa -= 0.5f * softplusf(spa ? -da : da);
        ampb -= 0.5f * softplusf(spb ? -db : db);
        if (role == 0) { tok0 = sp0; tok1 = sp1; tok2 = sp2; tok3 = sp3; }
    }

    if (lane == 0) {
        int o0 = base + (role ? 2 : 0);
        if (o0 < B)     out[o0]     = ampa;
        if (o0 + 1 < B) out[o0 + 1] = ampb;
    }
}

// ---------------------------------------------------------------------------
extern "C" void kernel_launch(void* const* d_in, const int* in_sizes, int n_in,
                              void* d_out, int out_size) {
    const int*   s  = (const int*)d_in[0];
    const float* W0 = (const float*)d_in[1];
    const float* b0 = (const float*)d_in[2];
    const float* Wi = (const float*)d_in[3];
    const float* Wh = (const float*)d_in[4];
    const float* bh = (const float*)d_in[5];
    const float* Wa = (const float*)d_in[6];
    const float* ba = (const float*)d_in[7];

    int B = out_size;
    int L = (B > 0) ? in_sizes[0] / B : 0;

    prep_kernel<<<67, 256>>>(W0, b0, Wi, Wh, bh, Wa, ba);

    int grid = (B + 15) / 16;
    lstm_kernel<<<grid, 256>>>(s, (float*)d_out, B, L);
}